// round 8
// baseline (speedup 1.0000x reference)
#include <cuda_runtime.h>
#include <cuda_fp16.h>
#include <cstdint>

// ---------------------------------------------------------------------------
// LongTermMemory: fp16 HMMA GEMMs with 64x64 warp tiles (smem-traffic
// optimized: 2x2 warp grid halves cross-warp fragment redundancy) +
// flash-style sliding-window attention (unchanged from R7).
// ---------------------------------------------------------------------------

constexpr int M_TOT = 4096;
constexpr int DIMC  = 1024;
constexpr int SEQ   = 2048;

// ---------------- scratch ----------------
__device__ __half g_xh[M_TOT * DIMC];
__device__ __half g_h[M_TOT * DIMC];
__device__ __half g_m[M_TOT * DIMC];
__device__ __half g_qkvh[3][M_TOT * DIMC];
__device__ float g_bqkv[3 * DIMC];
__device__ __half g_w[5][DIMC * DIMC];   // transposed: Wt[n][k], fp16

// ---------------------------------------------------------------------------
// helpers
// ---------------------------------------------------------------------------
__device__ __forceinline__ uint32_t smem_u32(const void* p) {
    uint32_t a;
    asm("{ .reg .u64 t; cvta.to.shared.u64 t, %1; cvt.u32.u64 %0, t; }"
        : "=r"(a) : "l"(p));
    return a;
}
__device__ __forceinline__ void cp_async16(uint32_t saddr, const void* gaddr) {
    asm volatile("cp.async.cg.shared.global [%0], [%1], 16;"
                 :: "r"(saddr), "l"(gaddr));
}
#define CP_COMMIT()  asm volatile("cp.async.commit_group;" ::: "memory")
#define CP_WAIT(N)   asm volatile("cp.async.wait_group %0;" :: "n"(N) : "memory")

__device__ __forceinline__ void ldmatrix_x4(uint32_t& r0, uint32_t& r1,
                                            uint32_t& r2, uint32_t& r3,
                                            uint32_t addr) {
    asm volatile("ldmatrix.sync.aligned.m8n8.x4.shared.b16 {%0,%1,%2,%3}, [%4];"
                 : "=r"(r0), "=r"(r1), "=r"(r2), "=r"(r3) : "r"(addr));
}
__device__ __forceinline__ void ldmatrix_x2(uint32_t& r0, uint32_t& r1,
                                            uint32_t addr) {
    asm volatile("ldmatrix.sync.aligned.m8n8.x2.shared.b16 {%0,%1}, [%2];"
                 : "=r"(r0), "=r"(r1) : "r"(addr));
}
__device__ __forceinline__ void ldmatrix_x4_trans(uint32_t& r0, uint32_t& r1,
                                                  uint32_t& r2, uint32_t& r3,
                                                  uint32_t addr) {
    asm volatile("ldmatrix.sync.aligned.m8n8.x4.trans.shared.b16 {%0,%1,%2,%3}, [%4];"
                 : "=r"(r0), "=r"(r1), "=r"(r2), "=r"(r3) : "r"(addr));
}

__device__ __forceinline__ void mma16816(float* d, const uint32_t* a,
                                         uint32_t b0, uint32_t b1) {
    asm volatile(
        "mma.sync.aligned.m16n8k16.row.col.f32.f16.f16.f32 "
        "{%0,%1,%2,%3}, {%4,%5,%6,%7}, {%8,%9}, {%0,%1,%2,%3};"
        : "+f"(d[0]), "+f"(d[1]), "+f"(d[2]), "+f"(d[3])
        : "r"(a[0]), "r"(a[1]), "r"(a[2]), "r"(a[3]), "r"(b0), "r"(b1));
}

// ---------------------------------------------------------------------------
// prep kernel: x->fp16, 5 weight transposes, qkv bias concat.
// ---------------------------------------------------------------------------
__global__ __launch_bounds__(256)
void prep_kernel(const float* __restrict__ x,
                 const float* __restrict__ w1, const float* __restrict__ w2,
                 const float* __restrict__ qw, const float* __restrict__ kw,
                 const float* __restrict__ vw,
                 const float* __restrict__ qb, const float* __restrict__ kb,
                 const float* __restrict__ vb,
                 __half* __restrict__ xh, __half* __restrict__ wt,
                 float* __restrict__ bqkv)
{
    const int b = blockIdx.x;
    const int tid = threadIdx.x;
    if (b < 4096) {
        const int row0 = (b >> 5) << 5;
        const int col0 = (b & 31) << 5;
        const int r = tid >> 3;
        const int c = (tid & 7) << 2;
        const size_t o = (size_t)(row0 + r) * DIMC + col0 + c;
        float4 v = *(const float4*)(x + o);
        __half2* hp = (__half2*)(xh + o);
        hp[0] = __floats2half2_rn(v.x, v.y);
        hp[1] = __floats2half2_rn(v.z, v.w);
    } else if (b < 4096 + 5120) {
        __shared__ float t[32][33];
        const int wb = b - 4096;
        const int wi = wb >> 10;
        const int within = wb & 1023;
        const int n0 = (within & 31) << 5;
        const int k0 = (within >> 5) << 5;
        const float* W = (wi == 0) ? w1 : (wi == 1) ? w2 :
                         (wi == 2) ? qw : (wi == 3) ? kw : vw;
        __half* out = wt + (size_t)wi * DIMC * DIMC;
        const int tx = tid & 31, ty = tid >> 5;
        #pragma unroll
        for (int i = ty; i < 32; i += 8)
            t[i][tx] = W[(size_t)(k0 + i) * DIMC + n0 + tx];
        __syncthreads();
        #pragma unroll
        for (int i = ty; i < 32; i += 8)
            out[(size_t)(n0 + i) * DIMC + k0 + tx] = __float2half_rn(t[tx][i]);
    } else {
        for (int i = tid; i < DIMC; i += 256) {
            bqkv[i]            = qb[i];
            bqkv[DIMC + i]     = kb[i];
            bqkv[2 * DIMC + i] = vb[i];
        }
    }
}

// ---------------------------------------------------------------------------
// HMMA GEMM v2: CTA 128x128, 4 warps (2x2), warp tile 64x64, BK=32,
// 3-stage cp.async, 128 threads, 2 CTAs/SM.
// ---------------------------------------------------------------------------
constexpr int BK = 32;
constexpr int STRIDE = 40;
constexpr int TILE_E = 128 * STRIDE;
constexpr int TILE_B = TILE_E * 2;
constexpr int STAGE_B = 2 * TILE_B;
constexpr int GEMM_SMEM = 3 * STAGE_B;   // 61440 B

template <int RELU, int OUT_F32, int NSTACK>
__global__ __launch_bounds__(128, 2)
void gemm_f16_kernel(const __half* __restrict__ A_h,
                     const __half* __restrict__ B_base,
                     const float* __restrict__ bias_base,
                     float* __restrict__ Cf_base,
                     __half* __restrict__ Ch_base)
{
    extern __shared__ __half sm[];
    const uint32_t sb = smem_u32(sm);

    const int tid  = threadIdx.x;
    const int wid  = tid >> 5;
    const int lane = tid & 31;
    int bx = blockIdx.x;
    const int by = blockIdx.y;
    int wsel = 0;
    if (NSTACK > 1) { wsel = bx >> 3; bx &= 7; }

    const __half* B   = B_base + (size_t)wsel * DIMC * DIMC;
    const float* bias = bias_base + wsel * DIMC;
    float* Cf = OUT_F32 ? (Cf_base + (size_t)wsel * M_TOT * DIMC) : nullptr;
    __half* Ch = OUT_F32 ? nullptr : (Ch_base + (size_t)wsel * M_TOT * DIMC);

    const int wr = wid >> 1;       // 0..1 -> m offset 64*wr
    const int wc = wid & 1;        // 0..1 -> n offset 64*wc
    const int g   = lane >> 2;
    const int tig = lane & 3;

    // cp.async: thread -> row tid, 4 x 16B spans A and B
    const __half* gA = A_h + (size_t)(by * 128 + tid) * DIMC;
    const __half* gB = B   + (size_t)(bx * 128 + tid) * DIMC;
    const uint32_t sofs = tid * STRIDE * 2;

    auto load_stage = [&](int buf, int kt) {
        const uint32_t s0 = sb + buf * STAGE_B + sofs;
        const int go = kt * BK;
        #pragma unroll
        for (int c = 0; c < 4; c++) {
            cp_async16(s0 + c * 16,          gA + go + c * 8);
            cp_async16(s0 + TILE_B + c * 16, gB + go + c * 8);
        }
    };

    // ldmatrix lane mapping
    const int lr15 = lane & 15;
    const int lk8  = (lane >> 4) << 3;
    const uint32_t aBase = ((uint32_t)(wr * 64 + lr15) * STRIDE + lk8) * 2;
    const uint32_t bBase = ((uint32_t)(wc * 64 + lr15) * STRIDE + lk8) * 2 + TILE_B;

    float acc[4][8][4];
    #pragma unroll
    for (int i = 0; i < 4; i++)
        #pragma unroll
        for (int j = 0; j < 8; j++)
            #pragma unroll
            for (int r = 0; r < 4; r++) acc[i][j][r] = 0.0f;

    load_stage(0, 0); CP_COMMIT();
    load_stage(1, 1); CP_COMMIT();

    constexpr int NKT = DIMC / BK;   // 32
    int buf = 0;
    for (int kt = 0; kt < NKT; kt++) {
        CP_WAIT(1);
        __syncthreads();
        if (kt + 2 < NKT) {
            int nb = buf + 2; if (nb >= 3) nb -= 3;
            load_stage(nb, kt + 2);
        }
        CP_COMMIT();

        const uint32_t st = sb + buf * STAGE_B;

        #pragma unroll
        for (int s = 0; s < 2; s++) {
            const uint32_t kc = (uint32_t)(s * 16) * 2;
            uint32_t ah[4][4], bf[4][4];
            #pragma unroll
            for (int i = 0; i < 4; i++) {
                const uint32_t ro = st + aBase + (uint32_t)(i * 16 * STRIDE) * 2 + kc;
                ldmatrix_x4(ah[i][0], ah[i][1], ah[i][2], ah[i][3], ro);
            }
            #pragma unroll
            for (int jj = 0; jj < 4; jj++) {
                const uint32_t ro = st + bBase + (uint32_t)(jj * 16 * STRIDE) * 2 + kc;
                ldmatrix_x4(bf[jj][0], bf[jj][1], bf[jj][2], bf[jj][3], ro);
            }
            #pragma unroll
            for (int i = 0; i < 4; i++)
                #pragma unroll
                for (int j = 0; j < 8; j++) {
                    const int jj = j >> 1, sel = j & 1;
                    mma16816(acc[i][j], ah[i], bf[jj][sel], bf[jj][sel + 2]);
                }
        }
        if (++buf == 3) buf = 0;
    }

    // ---- epilogue ----
    #pragma unroll
    for (int i = 0; i < 4; i++) {
        const int mg0 = by * 128 + wr * 64 + i * 16 + g;
        #pragma unroll
        for (int j = 0; j < 8; j++) {
            const int ng = bx * 128 + wc * 64 + j * 8 + tig * 2;
            const float b0 = __ldg(bias + ng);
            const float b1 = __ldg(bias + ng + 1);
            float v00 = acc[i][j][0] + b0;
            float v01 = acc[i][j][1] + b1;
            float v10 = acc[i][j][2] + b0;
            float v11 = acc[i][j][3] + b1;
            if (RELU) {
                v00 = fmaxf(v00, 0.0f); v01 = fmaxf(v01, 0.0f);
                v10 = fmaxf(v10, 0.0f); v11 = fmaxf(v11, 0.0f);
            }
            const size_t o0 = (size_t)mg0 * DIMC + ng;
            const size_t o1 = (size_t)(mg0 + 8) * DIMC + ng;
            if (OUT_F32) {
                *(float2*)(Cf + o0) = make_float2(v00, v01);
                *(float2*)(Cf + o1) = make_float2(v10, v11);
            } else {
                *(__half2*)(Ch + o0) = __floats2half2_rn(v00, v01);
                *(__half2*)(Ch + o1) = __floats2half2_rn(v10, v11);
            }
        }
    }
}

// ---------------------------------------------------------------------------
// Flash-style sliding-window attention (as R7).
// ---------------------------------------------------------------------------
constexpr int QB = 32;
constexpr int KBAND = 96;
constexpr int BKD = 64;
constexpr int DC = 128;

constexpr int QS_STRIDE = 72;
constexpr int VS_STRIDE = 136;
constexpr int SF_STRIDE = 100;
constexpr int PS_STRIDE = 104;

constexpr int Q_ST = QB * QS_STRIDE * 2;
constexpr int K_ST = KBAND * QS_STRIDE * 2;
constexpr int V_ST = KBAND * VS_STRIDE * 2;
constexpr int OFF_Q = 0;
constexpr int OFF_K = OFF_Q + 3 * Q_ST;
constexpr int OFF_S = OFF_K + 3 * K_ST;
constexpr int OFF_P = OFF_S + QB * SF_STRIDE * 4;
constexpr int OFF_V = OFF_P + QB * PS_STRIDE * 2;
constexpr int SWA_SMEM = OFF_V + 3 * V_ST;

__global__ __launch_bounds__(256, 1)
void swa_flash_kernel(const __half* __restrict__ q,
                      const __half* __restrict__ k,
                      const __half* __restrict__ v,
                      float* __restrict__ out)
{
    extern __shared__ char smc[];
    const uint32_t sb = smem_u32(smc);

    const int tid  = threadIdx.x;
    const int wid  = tid >> 5;
    const int lane = tid & 31;
    const int bid  = blockIdx.x;
    const int batch = bid >> 6;
    const int s0 = (bid & 63) * QB;

    const int wr = wid >> 2;
    const int wc = wid & 3;
    const int lr15 = lane & 15;
    const int lk8  = (lane >> 4) << 3;

    const size_t qbase = (size_t)(batch * SEQ + s0) * DIMC;
    const size_t kvbase = (size_t)batch * SEQ * DIMC;

    const int qrow = tid >> 3;
    const int qch  = (tid & 7) * 8;
    auto load_qk = [&](int buf, int kt) {
        const int d0 = kt * BKD + qch;
        cp_async16(sb + OFF_Q + buf * Q_ST + (qrow * QS_STRIDE + qch) * 2,
                   q + qbase + (size_t)qrow * DIMC + d0);
        #pragma unroll
        for (int i = 0; i < 3; i++) {
            const int krow = qrow + 32 * i;
            int jg = s0 - 32 + krow;
            jg = jg < 0 ? 0 : (jg >= SEQ ? SEQ - 1 : jg);
            cp_async16(sb + OFF_K + buf * K_ST + (krow * QS_STRIDE + qch) * 2,
                       k + kvbase + (size_t)jg * DIMC + d0);
        }
    };

    float accS[3][4];
    #pragma unroll
    for (int j = 0; j < 3; j++)
        #pragma unroll
        for (int r = 0; r < 4; r++) accS[j][r] = 0.0f;

    load_qk(0, 0); CP_COMMIT();
    load_qk(1, 1); CP_COMMIT();

    constexpr int NKT1 = DIMC / BKD;
    int buf = 0;
    for (int kt = 0; kt < NKT1; kt++) {
        CP_WAIT(1);
        __syncthreads();
        if (kt + 2 < NKT1) {
            int nb = buf + 2; if (nb >= 3) nb -= 3;
            load_qk(nb, kt + 2);
        }
        CP_COMMIT();

        const uint32_t sq = sb + OFF_Q + buf * Q_ST;
        const uint32_t sk = sb + OFF_K + buf * K_ST;

        #pragma unroll
        for (int ks = 0; ks < 4; ks++) {
            uint32_t a[4];
            ldmatrix_x4(a[0], a[1], a[2], a[3],
                        sq + ((uint32_t)(wr * 16 + lr15) * QS_STRIDE + ks * 16 + lk8) * 2);
            uint32_t br[3][2];
            #pragma unroll
            for (int gN = 0; gN < 3; gN++) {
                ldmatrix_x2(br[gN][0], br[gN][1],
                            sk + ((uint32_t)(wc * 24 + gN * 8 + (lane & 7)) * QS_STRIDE
                                  + ks * 16 + ((lane >> 3) & 1) * 8) * 2);
            }
            #pragma unroll
            for (int gN = 0; gN < 3; gN++)
                mma16816(accS[gN], a, br[gN][0], br[gN][1]);
        }
        if (++buf == 3) buf = 0;
    }

    {
        float* Sf = (float*)(smc + OFF_S);
        const int r0 = wr * 16 + (lane >> 2);
        const int c0 = wc * 24 + (lane & 3) * 2;
        #pragma unroll
        for (int gN = 0; gN < 3; gN++) {
            #pragma unroll
            for (int half = 0; half < 2; half++) {
                const int qi = r0 + half * 8;
                #pragma unroll
                for (int cc = 0; cc < 2; cc++) {
                    const int kj = c0 + gN * 8 + cc;
                    const int jg = s0 - 32 + kj;
                    const int d  = kj - qi;
                    const bool valid = (jg >= 0) && (jg < SEQ) && (d >= 0) && (d <= 64);
                    Sf[qi * SF_STRIDE + kj] =
                        valid ? accS[gN][half * 2 + cc] * 0.03125f : -1e30f;
                }
            }
        }
    }
    __syncthreads();

    {
        float* Sf = (float*)(smc + OFF_S);
        __half* Ps = (__half*)(smc + OFF_P);
        const int srow = tid >> 3;
        const int ssub = tid & 7;
        float vals[12];
        float mx = -1e30f;
        #pragma unroll
        for (int i = 0; i < 12; i++) {
            vals[i] = Sf[srow * SF_STRIDE + ssub * 12 + i];
            mx = fmaxf(mx, vals[i]);
        }
        #pragma unroll
        for (int off = 4; off; off >>= 1)
            mx = fmaxf(mx, __shfl_xor_sync(0xffffffffu, mx, off));
        float sum = 0.0f;
        #pragma unroll
        for (int i = 0; i < 12; i++) {
            vals[i] = __expf(vals[i] - mx);
            sum += vals[i];
        }
        #pragma unroll
        for (int off = 4; off; off >>= 1)
            sum += __shfl_xor_sync(0xffffffffu, sum, off);
        const float inv = 1.0f / sum;
        #pragma unroll
        for (int i = 0; i < 12; i++)
            Ps[srow * PS_STRIDE + ssub * 12 + i] = __float2half(vals[i] * inv);
    }
    CP_WAIT(0);
    __syncthreads();

    const int vrow16 = tid >> 4;
    const int vch    = (tid & 15) * 8;
    auto load_v = [&](int vbuf, int c) {
        const int d0 = c * DC + vch;
        #pragma unroll
        for (int i = 0; i < 6; i++) {
            const int krow = vrow16 + 16 * i;
            int jg = s0 - 32 + krow;
            jg = jg < 0 ? 0 : (jg >= SEQ ? SEQ - 1 : jg);
            cp_async16(sb + OFF_V + vbuf * V_ST + (krow * VS_STRIDE + vch) * 2,
                       v + kvbase + (size_t)jg * DIMC + d0);
        }
    };

    load_v(0, 0); CP_COMMIT();
    load_v(1, 1); CP_COMMIT();

    const uint32_t psb = sb + OFF_P;
    int vb = 0;
    constexpr int NC = DIMC / DC;
    for (int c = 0; c < NC; c++) {
        CP_WAIT(1);
        __syncthreads();
        if (c + 2 < NC) {
            int nb = vb + 2; if (nb >= 3) nb -= 3;
            load_v(nb, c + 2);
        }
        CP_COMMIT();

        const uint32_t sv = sb + OFF_V + vb * V_ST;

        float acc2[4][4];
        #pragma unroll
        for (int j = 0; j < 4; j++)
            #pragma unroll
            for (int r = 0; r < 4; r++) acc2[j][r] = 0.0f;

        #pragma unroll
        for (int ks = 0; ks < 6; ks++) {
            uint32_t p[4];
            ldmatrix_x4(p[0], p[1], p[2], p[3],
                        psb + ((uint32_t)(wr * 16 + lr15) * PS_STRIDE + ks * 16 + lk8) * 2);
            uint32_t vbf[2][4];
            #pragma unroll
            for (int h = 0; h < 2; h++) {
                ldmatrix_x4_trans(vbf[h][0], vbf[h][1], vbf[h][2], vbf[h][3],
                                  sv + ((uint32_t)(ks * 16 + lr15) * VS_STRIDE
                                        + wc * 32 + h * 16 + lk8) * 2);
            }
            #pragma unroll
            for (int j = 0; j < 4; j++)
                mma16816(acc2[j], p, vbf[j >> 1][(j & 1) * 2], vbf[j >> 1][(j & 1) * 2 + 1]);
        }

        const int r0 = wr * 16 + (lane >> 2);
        #pragma unroll
        for (int j = 0; j < 4; j++) {
            const int col = c * DC + wc * 32 + j * 8 + (lane & 3) * 2;
            const size_t o0 = qbase + (size_t)r0 * DIMC + col;
            const size_t o1 = qbase + (size_t)(r0 + 8) * DIMC + col;
            *(float2*)(out + o0) = make_float2(acc2[j][0], acc2[j][1]);
            *(float2*)(out + o1) = make_float2(acc2[j][2], acc2[j][3]);
        }
        if (++vb == 3) vb = 0;
    }
}

// ---------------------------------------------------------------------------
// launch
// ---------------------------------------------------------------------------
extern "C" void kernel_launch(void* const* d_in, const int* in_sizes, int n_in,
                              void* d_out, int out_size)
{
    const float* x     = (const float*)d_in[0];
    const float* nm_w1 = (const float*)d_in[1];
    const float* nm_b1 = (const float*)d_in[2];
    const float* nm_w2 = (const float*)d_in[3];
    const float* nm_b2 = (const float*)d_in[4];
    const float* q_w   = (const float*)d_in[5];
    const float* q_b   = (const float*)d_in[6];
    const float* k_w   = (const float*)d_in[7];
    const float* k_b   = (const float*)d_in[8];
    const float* v_w   = (const float*)d_in[9];
    const float* v_b   = (const float*)d_in[10];
    float* out = (float*)d_out;

    __half *xh, *h, *m, *w, *qkvh;
    float *bqkv;
    cudaGetSymbolAddress((void**)&xh, g_xh);
    cudaGetSymbolAddress((void**)&h, g_h);
    cudaGetSymbolAddress((void**)&m, g_m);
    cudaGetSymbolAddress((void**)&w, g_w);
    cudaGetSymbolAddress((void**)&qkvh, g_qkvh);
    cudaGetSymbolAddress((void**)&bqkv, g_bqkv);

    cudaFuncSetAttribute(gemm_f16_kernel<1,0,1>, cudaFuncAttributeMaxDynamicSharedMemorySize, GEMM_SMEM);
    cudaFuncSetAttribute(gemm_f16_kernel<0,0,1>, cudaFuncAttributeMaxDynamicSharedMemorySize, GEMM_SMEM);
    cudaFuncSetAttribute(gemm_f16_kernel<0,0,3>, cudaFuncAttributeMaxDynamicSharedMemorySize, GEMM_SMEM);
    cudaFuncSetAttribute(swa_flash_kernel, cudaFuncAttributeMaxDynamicSharedMemorySize, SWA_SMEM);

    constexpr size_t WSZ = (size_t)DIMC * DIMC;

    prep_kernel<<<4096 + 5 * 1024 + 1, 256>>>(x, nm_w1, nm_w2, q_w, k_w, v_w,
                                              q_b, k_b, v_b, xh, w, bqkv);

    dim3 grid(8, 32);
    gemm_f16_kernel<1,0,1><<<grid, 128, GEMM_SMEM>>>(xh, w + 0 * WSZ, nm_b1, nullptr, h);
    gemm_f16_kernel<0,0,1><<<grid, 128, GEMM_SMEM>>>(h,  w + 1 * WSZ, nm_b2, nullptr, m);

    dim3 gridQKV(24, 32);
    gemm_f16_kernel<0,0,3><<<gridQKV, 128, GEMM_SMEM>>>(m, w + 2 * WSZ, bqkv, nullptr, qkvh);

    const __half* qh = qkvh;
    const __half* kh = qkvh + (size_t)M_TOT * DIMC;
    const __half* vh = qkvh + 2 * (size_t)M_TOT * DIMC;
    swa_flash_kernel<<<128, 256, SWA_SMEM>>>(qh, kh, vh, out);
}

// round 9
// speedup vs baseline: 1.1110x; 1.1110x over previous
#include <cuda_runtime.h>
#include <cuda_fp16.h>
#include <cstdint>

// ---------------------------------------------------------------------------
// LongTermMemory: fp16 HMMA GEMMs — R7 config (256 thr, 2x4 warps, 64x32
// warp tiles, 2 CTA/SM) with BK=64 (16 k-iterations, halved barrier/wait
// overhead). Flash-style sliding-window attention unchanged.
// ---------------------------------------------------------------------------

constexpr int M_TOT = 4096;
constexpr int DIMC  = 1024;
constexpr int SEQ   = 2048;

// ---------------- scratch ----------------
__device__ __half g_xh[M_TOT * DIMC];
__device__ __half g_h[M_TOT * DIMC];
__device__ __half g_m[M_TOT * DIMC];
__device__ __half g_qkvh[3][M_TOT * DIMC];
__device__ float g_bqkv[3 * DIMC];
__device__ __half g_w[5][DIMC * DIMC];   // transposed: Wt[n][k], fp16

// ---------------------------------------------------------------------------
// helpers
// ---------------------------------------------------------------------------
__device__ __forceinline__ uint32_t smem_u32(const void* p) {
    uint32_t a;
    asm("{ .reg .u64 t; cvta.to.shared.u64 t, %1; cvt.u32.u64 %0, t; }"
        : "=r"(a) : "l"(p));
    return a;
}
__device__ __forceinline__ void cp_async16(uint32_t saddr, const void* gaddr) {
    asm volatile("cp.async.cg.shared.global [%0], [%1], 16;"
                 :: "r"(saddr), "l"(gaddr));
}
#define CP_COMMIT()  asm volatile("cp.async.commit_group;" ::: "memory")
#define CP_WAIT(N)   asm volatile("cp.async.wait_group %0;" :: "n"(N) : "memory")

__device__ __forceinline__ void ldmatrix_x4(uint32_t& r0, uint32_t& r1,
                                            uint32_t& r2, uint32_t& r3,
                                            uint32_t addr) {
    asm volatile("ldmatrix.sync.aligned.m8n8.x4.shared.b16 {%0,%1,%2,%3}, [%4];"
                 : "=r"(r0), "=r"(r1), "=r"(r2), "=r"(r3) : "r"(addr));
}
__device__ __forceinline__ void ldmatrix_x2(uint32_t& r0, uint32_t& r1,
                                            uint32_t addr) {
    asm volatile("ldmatrix.sync.aligned.m8n8.x2.shared.b16 {%0,%1}, [%2];"
                 : "=r"(r0), "=r"(r1) : "r"(addr));
}
__device__ __forceinline__ void ldmatrix_x4_trans(uint32_t& r0, uint32_t& r1,
                                                  uint32_t& r2, uint32_t& r3,
                                                  uint32_t addr) {
    asm volatile("ldmatrix.sync.aligned.m8n8.x4.trans.shared.b16 {%0,%1,%2,%3}, [%4];"
                 : "=r"(r0), "=r"(r1), "=r"(r2), "=r"(r3) : "r"(addr));
}

__device__ __forceinline__ void mma16816(float* d, const uint32_t* a,
                                         uint32_t b0, uint32_t b1) {
    asm volatile(
        "mma.sync.aligned.m16n8k16.row.col.f32.f16.f16.f32 "
        "{%0,%1,%2,%3}, {%4,%5,%6,%7}, {%8,%9}, {%0,%1,%2,%3};"
        : "+f"(d[0]), "+f"(d[1]), "+f"(d[2]), "+f"(d[3])
        : "r"(a[0]), "r"(a[1]), "r"(a[2]), "r"(a[3]), "r"(b0), "r"(b1));
}

// ---------------------------------------------------------------------------
// prep kernel: x->fp16, 5 weight transposes, qkv bias concat.
// ---------------------------------------------------------------------------
__global__ __launch_bounds__(256)
void prep_kernel(const float* __restrict__ x,
                 const float* __restrict__ w1, const float* __restrict__ w2,
                 const float* __restrict__ qw, const float* __restrict__ kw,
                 const float* __restrict__ vw,
                 const float* __restrict__ qb, const float* __restrict__ kb,
                 const float* __restrict__ vb,
                 __half* __restrict__ xh, __half* __restrict__ wt,
                 float* __restrict__ bqkv)
{
    const int b = blockIdx.x;
    const int tid = threadIdx.x;
    if (b < 4096) {
        const int row0 = (b >> 5) << 5;
        const int col0 = (b & 31) << 5;
        const int r = tid >> 3;
        const int c = (tid & 7) << 2;
        const size_t o = (size_t)(row0 + r) * DIMC + col0 + c;
        float4 v = *(const float4*)(x + o);
        __half2* hp = (__half2*)(xh + o);
        hp[0] = __floats2half2_rn(v.x, v.y);
        hp[1] = __floats2half2_rn(v.z, v.w);
    } else if (b < 4096 + 5120) {
        __shared__ float t[32][33];
        const int wb = b - 4096;
        const int wi = wb >> 10;
        const int within = wb & 1023;
        const int n0 = (within & 31) << 5;
        const int k0 = (within >> 5) << 5;
        const float* W = (wi == 0) ? w1 : (wi == 1) ? w2 :
                         (wi == 2) ? qw : (wi == 3) ? kw : vw;
        __half* out = wt + (size_t)wi * DIMC * DIMC;
        const int tx = tid & 31, ty = tid >> 5;
        #pragma unroll
        for (int i = ty; i < 32; i += 8)
            t[i][tx] = W[(size_t)(k0 + i) * DIMC + n0 + tx];
        __syncthreads();
        #pragma unroll
        for (int i = ty; i < 32; i += 8)
            out[(size_t)(n0 + i) * DIMC + k0 + tx] = __float2half_rn(t[tx][i]);
    } else {
        for (int i = tid; i < DIMC; i += 256) {
            bqkv[i]            = qb[i];
            bqkv[DIMC + i]     = kb[i];
            bqkv[2 * DIMC + i] = vb[i];
        }
    }
}

// ---------------------------------------------------------------------------
// HMMA GEMM: CTA 128x128, BK=64, 8 warps (2x4), warp tile 64x32,
// 3-stage cp.async, 256 threads, 2 CTAs/SM (2 x 110.6KB smem).
// ---------------------------------------------------------------------------
constexpr int BK = 64;
constexpr int STRIDE = 72;                        // elements (64 + 8 pad)
constexpr int TILE_E = 128 * STRIDE;              // 9216 el
constexpr int TILE_B = TILE_E * 2;                // 18432 B
constexpr int STAGE_B = 2 * TILE_B;               // 36864 B (A + B)
constexpr int GEMM_SMEM = 3 * STAGE_B;            // 110592 B

template <int RELU, int OUT_F32, int NSTACK>
__global__ __launch_bounds__(256, 2)
void gemm_f16_kernel(const __half* __restrict__ A_h,
                     const __half* __restrict__ B_base,
                     const float* __restrict__ bias_base,
                     float* __restrict__ Cf_base,
                     __half* __restrict__ Ch_base)
{
    extern __shared__ __half sm[];
    const uint32_t sb = smem_u32(sm);

    const int tid  = threadIdx.x;
    const int wid  = tid >> 5;
    const int lane = tid & 31;
    int bx = blockIdx.x;
    const int by = blockIdx.y;
    int wsel = 0;
    if (NSTACK > 1) { wsel = bx >> 3; bx &= 7; }

    const __half* B   = B_base + (size_t)wsel * DIMC * DIMC;
    const float* bias = bias_base + wsel * DIMC;
    float* Cf = OUT_F32 ? (Cf_base + (size_t)wsel * M_TOT * DIMC) : nullptr;
    __half* Ch = OUT_F32 ? nullptr : (Ch_base + (size_t)wsel * M_TOT * DIMC);

    const int wr = wid >> 2;       // 0..1 -> m offset 64*wr
    const int wc = wid & 3;        // 0..3 -> n offset 32*wc
    const int g   = lane >> 2;
    const int tig = lane & 3;

    // cp.async mapping: row = tid>>1, 32-el half = (tid&1)*32 (4 x 16B each tile)
    const int lrow  = tid >> 1;
    const int lhalf = (tid & 1) * 32;

    const __half* gA = A_h + (size_t)(by * 128 + lrow) * DIMC + lhalf;
    const __half* gB = B   + (size_t)(bx * 128 + lrow) * DIMC + lhalf;
    const uint32_t sofs = (lrow * STRIDE + lhalf) * 2;

    auto load_stage = [&](int buf, int kt) {
        const uint32_t s0 = sb + buf * STAGE_B + sofs;
        const int go = kt * BK;
        #pragma unroll
        for (int c = 0; c < 4; c++) {
            cp_async16(s0 + c * 16,          gA + go + c * 8);
            cp_async16(s0 + TILE_B + c * 16, gB + go + c * 8);
        }
    };

    // ldmatrix lane mapping
    const int lr15 = lane & 15;
    const int lk8  = (lane >> 4) << 3;
    const uint32_t aBase = ((uint32_t)(wr * 64 + lr15) * STRIDE + lk8) * 2;
    const uint32_t bBase = ((uint32_t)(wc * 32 + lr15) * STRIDE + lk8) * 2 + TILE_B;

    float acc[4][4][4];
    #pragma unroll
    for (int i = 0; i < 4; i++)
        #pragma unroll
        for (int j = 0; j < 4; j++)
            #pragma unroll
            for (int r = 0; r < 4; r++) acc[i][j][r] = 0.0f;

    load_stage(0, 0); CP_COMMIT();
    load_stage(1, 1); CP_COMMIT();

    constexpr int NKT = DIMC / BK;   // 16
    int buf = 0;
    for (int kt = 0; kt < NKT; kt++) {
        CP_WAIT(1);
        __syncthreads();
        if (kt + 2 < NKT) {
            int nb = buf + 2; if (nb >= 3) nb -= 3;
            load_stage(nb, kt + 2);
        }
        CP_COMMIT();

        const uint32_t st = sb + buf * STAGE_B;

        // two half-iterations of 32 K each (fragment batches of 2 k16 steps)
        #pragma unroll
        for (int hh = 0; hh < 2; hh++) {
            uint32_t ah[2][4][4], bf[2][2][4];
            #pragma unroll
            for (int s = 0; s < 2; s++) {
                const uint32_t kc = (uint32_t)(hh * 32 + s * 16) * 2;
                #pragma unroll
                for (int i = 0; i < 4; i++) {
                    const uint32_t ro = st + aBase + (uint32_t)(i * 16 * STRIDE) * 2 + kc;
                    ldmatrix_x4(ah[s][i][0], ah[s][i][1], ah[s][i][2], ah[s][i][3], ro);
                }
                #pragma unroll
                for (int jj = 0; jj < 2; jj++) {
                    const uint32_t ro = st + bBase + (uint32_t)(jj * 16 * STRIDE) * 2 + kc;
                    ldmatrix_x4(bf[s][jj][0], bf[s][jj][1], bf[s][jj][2], bf[s][jj][3], ro);
                }
            }
            #pragma unroll
            for (int s = 0; s < 2; s++)
                #pragma unroll
                for (int i = 0; i < 4; i++)
                    #pragma unroll
                    for (int j = 0; j < 4; j++) {
                        const int jj = j >> 1, sel = j & 1;
                        mma16816(acc[i][j], ah[s][i], bf[s][jj][sel], bf[s][jj][sel + 2]);
                    }
        }

        if (++buf == 3) buf = 0;
    }

    // ---- epilogue ----
    #pragma unroll
    for (int i = 0; i < 4; i++) {
        const int mg0 = by * 128 + wr * 64 + i * 16 + g;
        #pragma unroll
        for (int j = 0; j < 4; j++) {
            const int ng = bx * 128 + wc * 32 + j * 8 + tig * 2;
            const float b0 = __ldg(bias + ng);
            const float b1 = __ldg(bias + ng + 1);
            float v00 = acc[i][j][0] + b0;
            float v01 = acc[i][j][1] + b1;
            float v10 = acc[i][j][2] + b0;
            float v11 = acc[i][j][3] + b1;
            if (RELU) {
                v00 = fmaxf(v00, 0.0f); v01 = fmaxf(v01, 0.0f);
                v10 = fmaxf(v10, 0.0f); v11 = fmaxf(v11, 0.0f);
            }
            const size_t o0 = (size_t)mg0 * DIMC + ng;
            const size_t o1 = (size_t)(mg0 + 8) * DIMC + ng;
            if (OUT_F32) {
                *(float2*)(Cf + o0) = make_float2(v00, v01);
                *(float2*)(Cf + o1) = make_float2(v10, v11);
            } else {
                *(__half2*)(Ch + o0) = __floats2half2_rn(v00, v01);
                *(__half2*)(Ch + o1) = __floats2half2_rn(v10, v11);
            }
        }
    }
}

// ---------------------------------------------------------------------------
// Flash-style sliding-window attention (as R7).
// ---------------------------------------------------------------------------
constexpr int QB = 32;
constexpr int KBAND = 96;
constexpr int BKD = 64;
constexpr int DC = 128;

constexpr int QS_STRIDE = 72;
constexpr int VS_STRIDE = 136;
constexpr int SF_STRIDE = 100;
constexpr int PS_STRIDE = 104;

constexpr int Q_ST = QB * QS_STRIDE * 2;
constexpr int K_ST = KBAND * QS_STRIDE * 2;
constexpr int V_ST = KBAND * VS_STRIDE * 2;
constexpr int OFF_Q = 0;
constexpr int OFF_K = OFF_Q + 3 * Q_ST;
constexpr int OFF_S = OFF_K + 3 * K_ST;
constexpr int OFF_P = OFF_S + QB * SF_STRIDE * 4;
constexpr int OFF_V = OFF_P + QB * PS_STRIDE * 2;
constexpr int SWA_SMEM = OFF_V + 3 * V_ST;

__global__ __launch_bounds__(256, 1)
void swa_flash_kernel(const __half* __restrict__ q,
                      const __half* __restrict__ k,
                      const __half* __restrict__ v,
                      float* __restrict__ out)
{
    extern __shared__ char smc[];
    const uint32_t sb = smem_u32(smc);

    const int tid  = threadIdx.x;
    const int wid  = tid >> 5;
    const int lane = tid & 31;
    const int bid  = blockIdx.x;
    const int batch = bid >> 6;
    const int s0 = (bid & 63) * QB;

    const int wr = wid >> 2;
    const int wc = wid & 3;
    const int lr15 = lane & 15;
    const int lk8  = (lane >> 4) << 3;

    const size_t qbase = (size_t)(batch * SEQ + s0) * DIMC;
    const size_t kvbase = (size_t)batch * SEQ * DIMC;

    const int qrow = tid >> 3;
    const int qch  = (tid & 7) * 8;
    auto load_qk = [&](int buf, int kt) {
        const int d0 = kt * BKD + qch;
        cp_async16(sb + OFF_Q + buf * Q_ST + (qrow * QS_STRIDE + qch) * 2,
                   q + qbase + (size_t)qrow * DIMC + d0);
        #pragma unroll
        for (int i = 0; i < 3; i++) {
            const int krow = qrow + 32 * i;
            int jg = s0 - 32 + krow;
            jg = jg < 0 ? 0 : (jg >= SEQ ? SEQ - 1 : jg);
            cp_async16(sb + OFF_K + buf * K_ST + (krow * QS_STRIDE + qch) * 2,
                       k + kvbase + (size_t)jg * DIMC + d0);
        }
    };

    float accS[3][4];
    #pragma unroll
    for (int j = 0; j < 3; j++)
        #pragma unroll
        for (int r = 0; r < 4; r++) accS[j][r] = 0.0f;

    load_qk(0, 0); CP_COMMIT();
    load_qk(1, 1); CP_COMMIT();

    constexpr int NKT1 = DIMC / BKD;
    int buf = 0;
    for (int kt = 0; kt < NKT1; kt++) {
        CP_WAIT(1);
        __syncthreads();
        if (kt + 2 < NKT1) {
            int nb = buf + 2; if (nb >= 3) nb -= 3;
            load_qk(nb, kt + 2);
        }
        CP_COMMIT();

        const uint32_t sq = sb + OFF_Q + buf * Q_ST;
        const uint32_t sk = sb + OFF_K + buf * K_ST;

        #pragma unroll
        for (int ks = 0; ks < 4; ks++) {
            uint32_t a[4];
            ldmatrix_x4(a[0], a[1], a[2], a[3],
                        sq + ((uint32_t)(wr * 16 + lr15) * QS_STRIDE + ks * 16 + lk8) * 2);
            uint32_t br[3][2];
            #pragma unroll
            for (int gN = 0; gN < 3; gN++) {
                ldmatrix_x2(br[gN][0], br[gN][1],
                            sk + ((uint32_t)(wc * 24 + gN * 8 + (lane & 7)) * QS_STRIDE
                                  + ks * 16 + ((lane >> 3) & 1) * 8) * 2);
            }
            #pragma unroll
            for (int gN = 0; gN < 3; gN++)
                mma16816(accS[gN], a, br[gN][0], br[gN][1]);
        }
        if (++buf == 3) buf = 0;
    }

    {
        float* Sf = (float*)(smc + OFF_S);
        const int r0 = wr * 16 + (lane >> 2);
        const int c0 = wc * 24 + (lane & 3) * 2;
        #pragma unroll
        for (int gN = 0; gN < 3; gN++) {
            #pragma unroll
            for (int half = 0; half < 2; half++) {
                const int qi = r0 + half * 8;
                #pragma unroll
                for (int cc = 0; cc < 2; cc++) {
                    const int kj = c0 + gN * 8 + cc;
                    const int jg = s0 - 32 + kj;
                    const int d  = kj - qi;
                    const bool valid = (jg >= 0) && (jg < SEQ) && (d >= 0) && (d <= 64);
                    Sf[qi * SF_STRIDE + kj] =
                        valid ? accS[gN][half * 2 + cc] * 0.03125f : -1e30f;
                }
            }
        }
    }
    __syncthreads();

    {
        float* Sf = (float*)(smc + OFF_S);
        __half* Ps = (__half*)(smc + OFF_P);
        const int srow = tid >> 3;
        const int ssub = tid & 7;
        float vals[12];
        float mx = -1e30f;
        #pragma unroll
        for (int i = 0; i < 12; i++) {
            vals[i] = Sf[srow * SF_STRIDE + ssub * 12 + i];
            mx = fmaxf(mx, vals[i]);
        }
        #pragma unroll
        for (int off = 4; off; off >>= 1)
            mx = fmaxf(mx, __shfl_xor_sync(0xffffffffu, mx, off));
        float sum = 0.0f;
        #pragma unroll
        for (int i = 0; i < 12; i++) {
            vals[i] = __expf(vals[i] - mx);
            sum += vals[i];
        }
        #pragma unroll
        for (int off = 4; off; off >>= 1)
            sum += __shfl_xor_sync(0xffffffffu, sum, off);
        const float inv = 1.0f / sum;
        #pragma unroll
        for (int i = 0; i < 12; i++)
            Ps[srow * PS_STRIDE + ssub * 12 + i] = __float2half(vals[i] * inv);
    }
    CP_WAIT(0);
    __syncthreads();

    const int vrow16 = tid >> 4;
    const int vch    = (tid & 15) * 8;
    auto load_v = [&](int vbuf, int c) {
        const int d0 = c * DC + vch;
        #pragma unroll
        for (int i = 0; i < 6; i++) {
            const int krow = vrow16 + 16 * i;
            int jg = s0 - 32 + krow;
            jg = jg < 0 ? 0 : (jg >= SEQ ? SEQ - 1 : jg);
            cp_async16(sb + OFF_V + vbuf * V_ST + (krow * VS_STRIDE + vch) * 2,
                       v + kvbase + (size_t)jg * DIMC + d0);
        }
    };

    load_v(0, 0); CP_COMMIT();
    load_v(1, 1); CP_COMMIT();

    const uint32_t psb = sb + OFF_P;
    int vb = 0;
    constexpr int NC = DIMC / DC;
    for (int c = 0; c < NC; c++) {
        CP_WAIT(1);
        __syncthreads();
        if (c + 2 < NC) {
            int nb = vb + 2; if (nb >= 3) nb -= 3;
            load_v(nb, c + 2);
        }
        CP_COMMIT();

        const uint32_t sv = sb + OFF_V + vb * V_ST;

        float acc2[4][4];
        #pragma unroll
        for (int j = 0; j < 4; j++)
            #pragma unroll
            for (int r = 0; r < 4; r++) acc2[j][r] = 0.0f;

        #pragma unroll
        for (int ks = 0; ks < 6; ks++) {
            uint32_t p[4];
            ldmatrix_x4(p[0], p[1], p[2], p[3],
                        psb + ((uint32_t)(wr * 16 + lr15) * PS_STRIDE + ks * 16 + lk8) * 2);
            uint32_t vbf[2][4];
            #pragma unroll
            for (int h = 0; h < 2; h++) {
                ldmatrix_x4_trans(vbf[h][0], vbf[h][1], vbf[h][2], vbf[h][3],
                                  sv + ((uint32_t)(ks * 16 + lr15) * VS_STRIDE
                                        + wc * 32 + h * 16 + lk8) * 2);
            }
            #pragma unroll
            for (int j = 0; j < 4; j++)
                mma16816(acc2[j], p, vbf[j >> 1][(j & 1) * 2], vbf[j >> 1][(j & 1) * 2 + 1]);
        }

        const int r0 = wr * 16 + (lane >> 2);
        #pragma unroll
        for (int j = 0; j < 4; j++) {
            const int col = c * DC + wc * 32 + j * 8 + (lane & 3) * 2;
            const size_t o0 = qbase + (size_t)r0 * DIMC + col;
            const size_t o1 = qbase + (size_t)(r0 + 8) * DIMC + col;
            *(float2*)(out + o0) = make_float2(acc2[j][0], acc2[j][1]);
            *(float2*)(out + o1) = make_float2(acc2[j][2], acc2[j][3]);
        }
        if (++vb == 3) vb = 0;
    }
}

// ---------------------------------------------------------------------------
// launch
// ---------------------------------------------------------------------------
extern "C" void kernel_launch(void* const* d_in, const int* in_sizes, int n_in,
                              void* d_out, int out_size)
{
    const float* x     = (const float*)d_in[0];
    const float* nm_w1 = (const float*)d_in[1];
    const float* nm_b1 = (const float*)d_in[2];
    const float* nm_w2 = (const float*)d_in[3];
    const float* nm_b2 = (const float*)d_in[4];
    const float* q_w   = (const float*)d_in[5];
    const float* q_b   = (const float*)d_in[6];
    const float* k_w   = (const float*)d_in[7];
    const float* k_b   = (const float*)d_in[8];
    const float* v_w   = (const float*)d_in[9];
    const float* v_b   = (const float*)d_in[10];
    float* out = (float*)d_out;

    __half *xh, *h, *m, *w, *qkvh;
    float *bqkv;
    cudaGetSymbolAddress((void**)&xh, g_xh);
    cudaGetSymbolAddress((void**)&h, g_h);
    cudaGetSymbolAddress((void**)&m, g_m);
    cudaGetSymbolAddress((void**)&w, g_w);
    cudaGetSymbolAddress((void**)&qkvh, g_qkvh);
    cudaGetSymbolAddress((void**)&bqkv, g_bqkv);

    cudaFuncSetAttribute(gemm_f16_kernel<1,0,1>, cudaFuncAttributeMaxDynamicSharedMemorySize, GEMM_SMEM);
    cudaFuncSetAttribute(gemm_f16_kernel<0,0,1>, cudaFuncAttributeMaxDynamicSharedMemorySize, GEMM_SMEM);
    cudaFuncSetAttribute(gemm_f16_kernel<0,0,3>, cudaFuncAttributeMaxDynamicSharedMemorySize, GEMM_SMEM);
    cudaFuncSetAttribute(swa_flash_kernel, cudaFuncAttributeMaxDynamicSharedMemorySize, SWA_SMEM);

    constexpr size_t WSZ = (size_t)DIMC * DIMC;

    prep_kernel<<<4096 + 5 * 1024 + 1, 256>>>(x, nm_w1, nm_w2, q_w, k_w, v_w,
                                              q_b, k_b, v_b, xh, w, bqkv);

    dim3 grid(8, 32);
    gemm_f16_kernel<1,0,1><<<grid, 256, GEMM_SMEM>>>(xh, w + 0 * WSZ, nm_b1, nullptr, h);
    gemm_f16_kernel<0,0,1><<<grid, 256, GEMM_SMEM>>>(h,  w + 1 * WSZ, nm_b2, nullptr, m);

    dim3 gridQKV(24, 32);
    gemm_f16_kernel<0,0,3><<<gridQKV, 256, GEMM_SMEM>>>(m, w + 2 * WSZ, bqkv, nullptr, qkvh);

    const __half* qh = qkvh;
    const __half* kh = qkvh + (size_t)M_TOT * DIMC;
    const __half* vh = qkvh + 2 * (size_t)M_TOT * DIMC;
    swa_flash_kernel<<<128, 256, SWA_SMEM>>>(qh, kh, vh, out);
}

// round 10
// speedup vs baseline: 1.3847x; 1.2464x over previous
#include <cuda_runtime.h>
#include <cuda_fp16.h>
#include <cstdint>

// ---------------------------------------------------------------------------
// LongTermMemory: fp16 HMMA GEMMs — R7 shape (BK=32, 256 thr, 2x4 warps,
// 3-stage cp.async, 2 CTA/SM) + register-double-buffered fragments so LDSM
// overlaps MMA. Flash-style sliding-window attention unchanged.
// ---------------------------------------------------------------------------

constexpr int M_TOT = 4096;
constexpr int DIMC  = 1024;
constexpr int SEQ   = 2048;

// ---------------- scratch ----------------
__device__ __half g_xh[M_TOT * DIMC];
__device__ __half g_h[M_TOT * DIMC];
__device__ __half g_m[M_TOT * DIMC];
__device__ __half g_qkvh[3][M_TOT * DIMC];
__device__ float g_bqkv[3 * DIMC];
__device__ __half g_w[5][DIMC * DIMC];   // transposed: Wt[n][k], fp16

// ---------------------------------------------------------------------------
// helpers
// ---------------------------------------------------------------------------
__device__ __forceinline__ uint32_t smem_u32(const void* p) {
    uint32_t a;
    asm("{ .reg .u64 t; cvta.to.shared.u64 t, %1; cvt.u32.u64 %0, t; }"
        : "=r"(a) : "l"(p));
    return a;
}
__device__ __forceinline__ void cp_async16(uint32_t saddr, const void* gaddr) {
    asm volatile("cp.async.cg.shared.global [%0], [%1], 16;"
                 :: "r"(saddr), "l"(gaddr));
}
#define CP_COMMIT()  asm volatile("cp.async.commit_group;" ::: "memory")
#define CP_WAIT(N)   asm volatile("cp.async.wait_group %0;" :: "n"(N) : "memory")

__device__ __forceinline__ void ldmatrix_x4(uint32_t& r0, uint32_t& r1,
                                            uint32_t& r2, uint32_t& r3,
                                            uint32_t addr) {
    asm volatile("ldmatrix.sync.aligned.m8n8.x4.shared.b16 {%0,%1,%2,%3}, [%4];"
                 : "=r"(r0), "=r"(r1), "=r"(r2), "=r"(r3) : "r"(addr));
}
__device__ __forceinline__ void ldmatrix_x2(uint32_t& r0, uint32_t& r1,
                                            uint32_t addr) {
    asm volatile("ldmatrix.sync.aligned.m8n8.x2.shared.b16 {%0,%1}, [%2];"
                 : "=r"(r0), "=r"(r1) : "r"(addr));
}
__device__ __forceinline__ void ldmatrix_x4_trans(uint32_t& r0, uint32_t& r1,
                                                  uint32_t& r2, uint32_t& r3,
                                                  uint32_t addr) {
    asm volatile("ldmatrix.sync.aligned.m8n8.x4.trans.shared.b16 {%0,%1,%2,%3}, [%4];"
                 : "=r"(r0), "=r"(r1), "=r"(r2), "=r"(r3) : "r"(addr));
}

__device__ __forceinline__ void mma16816(float* d, const uint32_t* a,
                                         uint32_t b0, uint32_t b1) {
    asm volatile(
        "mma.sync.aligned.m16n8k16.row.col.f32.f16.f16.f32 "
        "{%0,%1,%2,%3}, {%4,%5,%6,%7}, {%8,%9}, {%0,%1,%2,%3};"
        : "+f"(d[0]), "+f"(d[1]), "+f"(d[2]), "+f"(d[3])
        : "r"(a[0]), "r"(a[1]), "r"(a[2]), "r"(a[3]), "r"(b0), "r"(b1));
}

// ---------------------------------------------------------------------------
// prep kernel: x->fp16, 5 weight transposes, qkv bias concat.
// ---------------------------------------------------------------------------
__global__ __launch_bounds__(256)
void prep_kernel(const float* __restrict__ x,
                 const float* __restrict__ w1, const float* __restrict__ w2,
                 const float* __restrict__ qw, const float* __restrict__ kw,
                 const float* __restrict__ vw,
                 const float* __restrict__ qb, const float* __restrict__ kb,
                 const float* __restrict__ vb,
                 __half* __restrict__ xh, __half* __restrict__ wt,
                 float* __restrict__ bqkv)
{
    const int b = blockIdx.x;
    const int tid = threadIdx.x;
    if (b < 4096) {
        const int row0 = (b >> 5) << 5;
        const int col0 = (b & 31) << 5;
        const int r = tid >> 3;
        const int c = (tid & 7) << 2;
        const size_t o = (size_t)(row0 + r) * DIMC + col0 + c;
        float4 v = *(const float4*)(x + o);
        __half2* hp = (__half2*)(xh + o);
        hp[0] = __floats2half2_rn(v.x, v.y);
        hp[1] = __floats2half2_rn(v.z, v.w);
    } else if (b < 4096 + 5120) {
        __shared__ float t[32][33];
        const int wb = b - 4096;
        const int wi = wb >> 10;
        const int within = wb & 1023;
        const int n0 = (within & 31) << 5;
        const int k0 = (within >> 5) << 5;
        const float* W = (wi == 0) ? w1 : (wi == 1) ? w2 :
                         (wi == 2) ? qw : (wi == 3) ? kw : vw;
        __half* out = wt + (size_t)wi * DIMC * DIMC;
        const int tx = tid & 31, ty = tid >> 5;
        #pragma unroll
        for (int i = ty; i < 32; i += 8)
            t[i][tx] = W[(size_t)(k0 + i) * DIMC + n0 + tx];
        __syncthreads();
        #pragma unroll
        for (int i = ty; i < 32; i += 8)
            out[(size_t)(n0 + i) * DIMC + k0 + tx] = __float2half_rn(t[tx][i]);
    } else {
        for (int i = tid; i < DIMC; i += 256) {
            bqkv[i]            = qb[i];
            bqkv[DIMC + i]     = kb[i];
            bqkv[2 * DIMC + i] = vb[i];
        }
    }
}

// ---------------------------------------------------------------------------
// HMMA GEMM: CTA 128x128, BK=32, 8 warps (2x4), warp tile 64x32,
// 3-stage cp.async, register-double-buffered fragments, 2 CTAs/SM.
// ---------------------------------------------------------------------------
constexpr int BK = 32;
constexpr int STRIDE = 40;                        // elements (32 + 8 pad)
constexpr int TILE_E = 128 * STRIDE;              // 5120 el
constexpr int TILE_B = TILE_E * 2;                // 10240 B
constexpr int STAGE_B = 2 * TILE_B;               // 20480 B (A + B)
constexpr int GEMM_SMEM = 3 * STAGE_B;            // 61440 B

template <int RELU, int OUT_F32, int NSTACK>
__global__ __launch_bounds__(256, 2)
void gemm_f16_kernel(const __half* __restrict__ A_h,
                     const __half* __restrict__ B_base,
                     const float* __restrict__ bias_base,
                     float* __restrict__ Cf_base,
                     __half* __restrict__ Ch_base)
{
    extern __shared__ __half sm[];
    const uint32_t sb = smem_u32(sm);

    const int tid  = threadIdx.x;
    const int wid  = tid >> 5;
    const int lane = tid & 31;
    int bx = blockIdx.x;
    const int by = blockIdx.y;
    int wsel = 0;
    if (NSTACK > 1) { wsel = bx >> 3; bx &= 7; }

    const __half* B   = B_base + (size_t)wsel * DIMC * DIMC;
    const float* bias = bias_base + wsel * DIMC;
    float* Cf = OUT_F32 ? (Cf_base + (size_t)wsel * M_TOT * DIMC) : nullptr;
    __half* Ch = OUT_F32 ? nullptr : (Ch_base + (size_t)wsel * M_TOT * DIMC);

    const int wr = wid >> 2;       // 0..1 -> m offset 64*wr
    const int wc = wid & 3;        // 0..3 -> n offset 32*wc
    const int g   = lane >> 2;
    const int tig = lane & 3;

    // cp.async mapping: row = tid>>1, 16-el half = tid&1
    const int lrow = tid >> 1;
    const int lsel = (tid & 1) * 16;

    const __half* gA = A_h + (size_t)(by * 128 + lrow) * DIMC + lsel;
    const __half* gB = B   + (size_t)(bx * 128 + lrow) * DIMC + lsel;
    const uint32_t sofs = (lrow * STRIDE + lsel) * 2;

    auto load_stage = [&](int buf, int kt) {
        const uint32_t s0 = sb + buf * STAGE_B + sofs;
        const int go = kt * BK;
        cp_async16(s0,               gA + go);
        cp_async16(s0 + 16,          gA + go + 8);
        cp_async16(s0 + TILE_B,      gB + go);
        cp_async16(s0 + TILE_B + 16, gB + go + 8);
    };

    // ldmatrix lane mapping
    const int lr15 = lane & 15;
    const int lk8  = (lane >> 4) << 3;
    const uint32_t aBase = ((uint32_t)(wr * 64 + lr15) * STRIDE + lk8) * 2;
    const uint32_t bBase = ((uint32_t)(wc * 32 + lr15) * STRIDE + lk8) * 2 + TILE_B;

    // double-buffered fragment registers
    uint32_t ahf[2][4][4], bff[2][2][4];

    auto ld_frags = [&](int slot, uint32_t st, int s) {
        const uint32_t kc = (uint32_t)(s * 16) * 2;
        #pragma unroll
        for (int i = 0; i < 4; i++) {
            const uint32_t ro = st + aBase + (uint32_t)(i * 16 * STRIDE) * 2 + kc;
            ldmatrix_x4(ahf[slot][i][0], ahf[slot][i][1],
                        ahf[slot][i][2], ahf[slot][i][3], ro);
        }
        #pragma unroll
        for (int jj = 0; jj < 2; jj++) {
            const uint32_t ro = st + bBase + (uint32_t)(jj * 16 * STRIDE) * 2 + kc;
            ldmatrix_x4(bff[slot][jj][0], bff[slot][jj][1],
                        bff[slot][jj][2], bff[slot][jj][3], ro);
        }
    };

    float acc[4][4][4];
    #pragma unroll
    for (int i = 0; i < 4; i++)
        #pragma unroll
        for (int j = 0; j < 4; j++)
            #pragma unroll
            for (int r = 0; r < 4; r++) acc[i][j][r] = 0.0f;

    auto do_mma = [&](int slot) {
        #pragma unroll
        for (int i = 0; i < 4; i++)
            #pragma unroll
            for (int j = 0; j < 4; j++) {
                const int jj = j >> 1, sel = j & 1;
                mma16816(acc[i][j], ahf[slot][i],
                         bff[slot][jj][sel], bff[slot][jj][sel + 2]);
            }
    };

    load_stage(0, 0); CP_COMMIT();
    load_stage(1, 1); CP_COMMIT();
    CP_WAIT(1);
    __syncthreads();

    constexpr int NKT = DIMC / BK;   // 32
    int buf = 0;
    // preload fragments (kt=0, s=0)
    ld_frags(0, sb, 0);

    for (int kt = 0; kt < NKT; kt++) {
        const uint32_t st = sb + buf * STAGE_B;
        // prefetch s=1 fragments of current kt (overlaps with mma slot 0)
        ld_frags(1, st, 1);
        // issue gmem loads for kt+2 into the buffer everyone finished last iter
        if (kt + 2 < NKT) {
            int nb = buf + 2; if (nb >= 3) nb -= 3;
            load_stage(nb, kt + 2);
        }
        CP_COMMIT();

        do_mma(0);

        if (kt + 1 < NKT) {
            CP_WAIT(1);
            __syncthreads();
            int nb = buf + 1; if (nb == 3) nb = 0;
            // prefetch s=0 fragments of next kt (overlaps with mma slot 1)
            ld_frags(0, sb + nb * STAGE_B, 0);
            buf = nb;
        }

        do_mma(1);
    }

    // ---- epilogue ----
    #pragma unroll
    for (int i = 0; i < 4; i++) {
        const int mg0 = by * 128 + wr * 64 + i * 16 + g;
        #pragma unroll
        for (int j = 0; j < 4; j++) {
            const int ng = bx * 128 + wc * 32 + j * 8 + tig * 2;
            const float b0 = __ldg(bias + ng);
            const float b1 = __ldg(bias + ng + 1);
            float v00 = acc[i][j][0] + b0;
            float v01 = acc[i][j][1] + b1;
            float v10 = acc[i][j][2] + b0;
            float v11 = acc[i][j][3] + b1;
            if (RELU) {
                v00 = fmaxf(v00, 0.0f); v01 = fmaxf(v01, 0.0f);
                v10 = fmaxf(v10, 0.0f); v11 = fmaxf(v11, 0.0f);
            }
            const size_t o0 = (size_t)mg0 * DIMC + ng;
            const size_t o1 = (size_t)(mg0 + 8) * DIMC + ng;
            if (OUT_F32) {
                *(float2*)(Cf + o0) = make_float2(v00, v01);
                *(float2*)(Cf + o1) = make_float2(v10, v11);
            } else {
                *(__half2*)(Ch + o0) = __floats2half2_rn(v00, v01);
                *(__half2*)(Ch + o1) = __floats2half2_rn(v10, v11);
            }
        }
    }
}

// ---------------------------------------------------------------------------
// Flash-style sliding-window attention (as R7).
// ---------------------------------------------------------------------------
constexpr int QB = 32;
constexpr int KBAND = 96;
constexpr int BKD = 64;
constexpr int DC = 128;

constexpr int QS_STRIDE = 72;
constexpr int VS_STRIDE = 136;
constexpr int SF_STRIDE = 100;
constexpr int PS_STRIDE = 104;

constexpr int Q_ST = QB * QS_STRIDE * 2;
constexpr int K_ST = KBAND * QS_STRIDE * 2;
constexpr int V_ST = KBAND * VS_STRIDE * 2;
constexpr int OFF_Q = 0;
constexpr int OFF_K = OFF_Q + 3 * Q_ST;
constexpr int OFF_S = OFF_K + 3 * K_ST;
constexpr int OFF_P = OFF_S + QB * SF_STRIDE * 4;
constexpr int OFF_V = OFF_P + QB * PS_STRIDE * 2;
constexpr int SWA_SMEM = OFF_V + 3 * V_ST;

__global__ __launch_bounds__(256, 1)
void swa_flash_kernel(const __half* __restrict__ q,
                      const __half* __restrict__ k,
                      const __half* __restrict__ v,
                      float* __restrict__ out)
{
    extern __shared__ char smc[];
    const uint32_t sb = smem_u32(smc);

    const int tid  = threadIdx.x;
    const int wid  = tid >> 5;
    const int lane = tid & 31;
    const int bid  = blockIdx.x;
    const int batch = bid >> 6;
    const int s0 = (bid & 63) * QB;

    const int wr = wid >> 2;
    const int wc = wid & 3;
    const int lr15 = lane & 15;
    const int lk8  = (lane >> 4) << 3;

    const size_t qbase = (size_t)(batch * SEQ + s0) * DIMC;
    const size_t kvbase = (size_t)batch * SEQ * DIMC;

    const int qrow = tid >> 3;
    const int qch  = (tid & 7) * 8;
    auto load_qk = [&](int buf, int kt) {
        const int d0 = kt * BKD + qch;
        cp_async16(sb + OFF_Q + buf * Q_ST + (qrow * QS_STRIDE + qch) * 2,
                   q + qbase + (size_t)qrow * DIMC + d0);
        #pragma unroll
        for (int i = 0; i < 3; i++) {
            const int krow = qrow + 32 * i;
            int jg = s0 - 32 + krow;
            jg = jg < 0 ? 0 : (jg >= SEQ ? SEQ - 1 : jg);
            cp_async16(sb + OFF_K + buf * K_ST + (krow * QS_STRIDE + qch) * 2,
                       k + kvbase + (size_t)jg * DIMC + d0);
        }
    };

    float accS[3][4];
    #pragma unroll
    for (int j = 0; j < 3; j++)
        #pragma unroll
        for (int r = 0; r < 4; r++) accS[j][r] = 0.0f;

    load_qk(0, 0); CP_COMMIT();
    load_qk(1, 1); CP_COMMIT();

    constexpr int NKT1 = DIMC / BKD;
    int buf = 0;
    for (int kt = 0; kt < NKT1; kt++) {
        CP_WAIT(1);
        __syncthreads();
        if (kt + 2 < NKT1) {
            int nb = buf + 2; if (nb >= 3) nb -= 3;
            load_qk(nb, kt + 2);
        }
        CP_COMMIT();

        const uint32_t sq = sb + OFF_Q + buf * Q_ST;
        const uint32_t sk = sb + OFF_K + buf * K_ST;

        #pragma unroll
        for (int ks = 0; ks < 4; ks++) {
            uint32_t a[4];
            ldmatrix_x4(a[0], a[1], a[2], a[3],
                        sq + ((uint32_t)(wr * 16 + lr15) * QS_STRIDE + ks * 16 + lk8) * 2);
            uint32_t br[3][2];
            #pragma unroll
            for (int gN = 0; gN < 3; gN++) {
                ldmatrix_x2(br[gN][0], br[gN][1],
                            sk + ((uint32_t)(wc * 24 + gN * 8 + (lane & 7)) * QS_STRIDE
                                  + ks * 16 + ((lane >> 3) & 1) * 8) * 2);
            }
            #pragma unroll
            for (int gN = 0; gN < 3; gN++)
                mma16816(accS[gN], a, br[gN][0], br[gN][1]);
        }
        if (++buf == 3) buf = 0;
    }

    {
        float* Sf = (float*)(smc + OFF_S);
        const int r0 = wr * 16 + (lane >> 2);
        const int c0 = wc * 24 + (lane & 3) * 2;
        #pragma unroll
        for (int gN = 0; gN < 3; gN++) {
            #pragma unroll
            for (int half = 0; half < 2; half++) {
                const int qi = r0 + half * 8;
                #pragma unroll
                for (int cc = 0; cc < 2; cc++) {
                    const int kj = c0 + gN * 8 + cc;
                    const int jg = s0 - 32 + kj;
                    const int d  = kj - qi;
                    const bool valid = (jg >= 0) && (jg < SEQ) && (d >= 0) && (d <= 64);
                    Sf[qi * SF_STRIDE + kj] =
                        valid ? accS[gN][half * 2 + cc] * 0.03125f : -1e30f;
                }
            }
        }
    }
    __syncthreads();

    {
        float* Sf = (float*)(smc + OFF_S);
        __half* Ps = (__half*)(smc + OFF_P);
        const int srow = tid >> 3;
        const int ssub = tid & 7;
        float vals[12];
        float mx = -1e30f;
        #pragma unroll
        for (int i = 0; i < 12; i++) {
            vals[i] = Sf[srow * SF_STRIDE + ssub * 12 + i];
            mx = fmaxf(mx, vals[i]);
        }
        #pragma unroll
        for (int off = 4; off; off >>= 1)
            mx = fmaxf(mx, __shfl_xor_sync(0xffffffffu, mx, off));
        float sum = 0.0f;
        #pragma unroll
        for (int i = 0; i < 12; i++) {
            vals[i] = __expf(vals[i] - mx);
            sum += vals[i];
        }
        #pragma unroll
        for (int off = 4; off; off >>= 1)
            sum += __shfl_xor_sync(0xffffffffu, sum, off);
        const float inv = 1.0f / sum;
        #pragma unroll
        for (int i = 0; i < 12; i++)
            Ps[srow * PS_STRIDE + ssub * 12 + i] = __float2half(vals[i] * inv);
    }
    CP_WAIT(0);
    __syncthreads();

    const int vrow16 = tid >> 4;
    const int vch    = (tid & 15) * 8;
    auto load_v = [&](int vbuf, int c) {
        const int d0 = c * DC + vch;
        #pragma unroll
        for (int i = 0; i < 6; i++) {
            const int krow = vrow16 + 16 * i;
            int jg = s0 - 32 + krow;
            jg = jg < 0 ? 0 : (jg >= SEQ ? SEQ - 1 : jg);
            cp_async16(sb + OFF_V + vbuf * V_ST + (krow * VS_STRIDE + vch) * 2,
                       v + kvbase + (size_t)jg * DIMC + d0);
        }
    };

    load_v(0, 0); CP_COMMIT();
    load_v(1, 1); CP_COMMIT();

    const uint32_t psb = sb + OFF_P;
    int vb = 0;
    constexpr int NC = DIMC / DC;
    for (int c = 0; c < NC; c++) {
        CP_WAIT(1);
        __syncthreads();
        if (c + 2 < NC) {
            int nb = vb + 2; if (nb >= 3) nb -= 3;
            load_v(nb, c + 2);
        }
        CP_COMMIT();

        const uint32_t sv = sb + OFF_V + vb * V_ST;

        float acc2[4][4];
        #pragma unroll
        for (int j = 0; j < 4; j++)
            #pragma unroll
            for (int r = 0; r < 4; r++) acc2[j][r] = 0.0f;

        #pragma unroll
        for (int ks = 0; ks < 6; ks++) {
            uint32_t p[4];
            ldmatrix_x4(p[0], p[1], p[2], p[3],
                        psb + ((uint32_t)(wr * 16 + lr15) * PS_STRIDE + ks * 16 + lk8) * 2);
            uint32_t vbf[2][4];
            #pragma unroll
            for (int h = 0; h < 2; h++) {
                ldmatrix_x4_trans(vbf[h][0], vbf[h][1], vbf[h][2], vbf[h][3],
                                  sv + ((uint32_t)(ks * 16 + lr15) * VS_STRIDE
                                        + wc * 32 + h * 16 + lk8) * 2);
            }
            #pragma unroll
            for (int j = 0; j < 4; j++)
                mma16816(acc2[j], p, vbf[j >> 1][(j & 1) * 2], vbf[j >> 1][(j & 1) * 2 + 1]);
        }

        const int r0 = wr * 16 + (lane >> 2);
        #pragma unroll
        for (int j = 0; j < 4; j++) {
            const int col = c * DC + wc * 32 + j * 8 + (lane & 3) * 2;
            const size_t o0 = qbase + (size_t)r0 * DIMC + col;
            const size_t o1 = qbase + (size_t)(r0 + 8) * DIMC + col;
            *(float2*)(out + o0) = make_float2(acc2[j][0], acc2[j][1]);
            *(float2*)(out + o1) = make_float2(acc2[j][2], acc2[j][3]);
        }
        if (++vb == 3) vb = 0;
    }
}

// ---------------------------------------------------------------------------
// launch
// ---------------------------------------------------------------------------
extern "C" void kernel_launch(void* const* d_in, const int* in_sizes, int n_in,
                              void* d_out, int out_size)
{
    const float* x     = (const float*)d_in[0];
    const float* nm_w1 = (const float*)d_in[1];
    const float* nm_b1 = (const float*)d_in[2];
    const float* nm_w2 = (const float*)d_in[3];
    const float* nm_b2 = (const float*)d_in[4];
    const float* q_w   = (const float*)d_in[5];
    const float* q_b   = (const float*)d_in[6];
    const float* k_w   = (const float*)d_in[7];
    const float* k_b   = (const float*)d_in[8];
    const float* v_w   = (const float*)d_in[9];
    const float* v_b   = (const float*)d_in[10];
    float* out = (float*)d_out;

    __half *xh, *h, *m, *w, *qkvh;
    float *bqkv;
    cudaGetSymbolAddress((void**)&xh, g_xh);
    cudaGetSymbolAddress((void**)&h, g_h);
    cudaGetSymbolAddress((void**)&m, g_m);
    cudaGetSymbolAddress((void**)&w, g_w);
    cudaGetSymbolAddress((void**)&qkvh, g_qkvh);
    cudaGetSymbolAddress((void**)&bqkv, g_bqkv);

    cudaFuncSetAttribute(gemm_f16_kernel<1,0,1>, cudaFuncAttributeMaxDynamicSharedMemorySize, GEMM_SMEM);
    cudaFuncSetAttribute(gemm_f16_kernel<0,0,1>, cudaFuncAttributeMaxDynamicSharedMemorySize, GEMM_SMEM);
    cudaFuncSetAttribute(gemm_f16_kernel<0,0,3>, cudaFuncAttributeMaxDynamicSharedMemorySize, GEMM_SMEM);
    cudaFuncSetAttribute(swa_flash_kernel, cudaFuncAttributeMaxDynamicSharedMemorySize, SWA_SMEM);

    constexpr size_t WSZ = (size_t)DIMC * DIMC;

    prep_kernel<<<4096 + 5 * 1024 + 1, 256>>>(x, nm_w1, nm_w2, q_w, k_w, v_w,
                                              q_b, k_b, v_b, xh, w, bqkv);

    dim3 grid(8, 32);
    gemm_f16_kernel<1,0,1><<<grid, 256, GEMM_SMEM>>>(xh, w + 0 * WSZ, nm_b1, nullptr, h);
    gemm_f16_kernel<0,0,1><<<grid, 256, GEMM_SMEM>>>(h,  w + 1 * WSZ, nm_b2, nullptr, m);

    dim3 gridQKV(24, 32);
    gemm_f16_kernel<0,0,3><<<gridQKV, 256, GEMM_SMEM>>>(m, w + 2 * WSZ, bqkv, nullptr, qkvh);

    const __half* qh = qkvh;
    const __half* kh = qkvh + (size_t)M_TOT * DIMC;
    const __half* vh = qkvh + 2 * (size_t)M_TOT * DIMC;
    swa_flash_kernel<<<128, 256, SWA_SMEM>>>(qh, kh, vh, out);
}